// round 1
// baseline (speedup 1.0000x reference)
#include <cuda_runtime.h>

#define NPLANE 96
#define IMG_H 512
#define IMG_W 512
#define PLANE (IMG_H * IMG_W)
#define NSTRIP 3
#define NBLOCKS (NPLANE * NSTRIP)
#define TPB 128
#define SLOTS 13   // ring slots; 13 gives modular slack 2 over window 11 -> one sync/row

__device__ float  g_c1[NPLANE];
__device__ float  g_c2[NPLANE];
__device__ double g_part[NBLOCKS];

// ---------------------------------------------------------------------------
// Kernel 1: per-plane dynamic range -> c1, c2
// ---------------------------------------------------------------------------
__global__ void __launch_bounds__(1024) range_kernel(const float* __restrict__ pred,
                                                     const float* __restrict__ target) {
    __shared__ float smx[1024];
    __shared__ float smn[1024];
    const int plane = blockIdx.x;
    const float4* __restrict__ P = (const float4*)(pred   + (size_t)plane * PLANE);
    const float4* __restrict__ T = (const float4*)(target + (size_t)plane * PLANE);
    float mx = -1e30f, mn = 1e30f;
    const int n4 = PLANE / 4;
    for (int i = threadIdx.x; i < n4; i += 1024) {
        float4 a = P[i];
        float4 b = T[i];
        float lmx = fmaxf(fmaxf(fmaxf(a.x, b.x), fmaxf(a.y, b.y)),
                          fmaxf(fmaxf(a.z, b.z), fmaxf(a.w, b.w)));
        float lmn = fminf(fminf(fminf(a.x, b.x), fminf(a.y, b.y)),
                          fminf(fminf(a.z, b.z), fminf(a.w, b.w)));
        mx = fmaxf(mx, lmx);
        mn = fminf(mn, lmn);
    }
    smx[threadIdx.x] = mx;
    smn[threadIdx.x] = mn;
    __syncthreads();
    for (int s = 512; s > 0; s >>= 1) {
        if (threadIdx.x < s) {
            smx[threadIdx.x] = fmaxf(smx[threadIdx.x], smx[threadIdx.x + s]);
            smn[threadIdx.x] = fminf(smn[threadIdx.x], smn[threadIdx.x + s]);
        }
        __syncthreads();
    }
    if (threadIdx.x == 0) {
        float dr = fmaxf(smx[0] - smn[0], 1e-6f);
        float a = 0.01f * dr;
        float b = 0.03f * dr;
        g_c1[plane] = a * a;
        g_c2[plane] = b * b;
    }
}

// ---------------------------------------------------------------------------
// Kernel 2: fused separable box filters + SSIM loss partial sums
//   block = one plane strip (full 512 width, ~171 output rows)
//   thread t: horizontal box for x in [4t, 4t+4)  (register sliding window)
//             vertical running sums for columns {t, t+128, t+256, t+384}
// ---------------------------------------------------------------------------
__global__ void __launch_bounds__(TPB) ssim_kernel(const float* __restrict__ pred,
                                                   const float* __restrict__ target) {
    extern __shared__ float ring[];   // [SLOTS][4][512]

    const int bid   = blockIdx.x;
    const int plane = bid / NSTRIP;
    const int strip = bid % NSTRIP;
    const int y0    = strip * 171;
    const int R     = (strip == 2) ? 170 : 171;

    const float* __restrict__ P = pred   + (size_t)plane * PLANE;
    const float* __restrict__ T = target + (size_t)plane * PLANE;
    const float c1 = g_c1[plane];
    const float c2 = g_c2[plane];

    const int tid = threadIdx.x;
    const int x0  = tid * 4;

    float vU[4] = {0.f, 0.f, 0.f, 0.f};
    float vW[4] = {0.f, 0.f, 0.f, 0.f};
    float vA[4] = {0.f, 0.f, 0.f, 0.f};
    float vB[4] = {0.f, 0.f, 0.f, 0.f};
    float acc = 0.f;

    const float n1  = 1.0f / 121.0f;
    const float hn1 = 0.5f * n1;
    const float hn2 = 0.5f * n1 * n1;

    int wslot = 0;  // k % SLOTS
    int sslot = 2;  // (k - 11) % SLOTS == (k + 2) % SLOTS

    const int KMAX = R + 10;
    for (int k = 0; k < KMAX; ++k) {
        const int iy = y0 - 5 + k;

        float hu[4], hw[4], ha[4], hb[4];
        const bool inrow = (iy >= 0) && (iy < IMG_H);
        if (inrow) {
            const float* __restrict__ pr = P + (size_t)iy * IMG_W;
            const float* __restrict__ tr = T + (size_t)iy * IMG_W;
            float pv[20], tv[20];
            const int base = x0 - 8;
            if (base >= 0 && base + 20 <= IMG_W) {
                #pragma unroll
                for (int i = 0; i < 5; ++i) {
                    *(float4*)(pv + 4 * i) = __ldg((const float4*)(pr + base + 4 * i));
                    *(float4*)(tv + 4 * i) = __ldg((const float4*)(tr + base + 4 * i));
                }
            } else {
                #pragma unroll
                for (int i = 0; i < 20; ++i) {
                    int x = base + i;
                    bool ok = (x >= 0) && (x < IMG_W);
                    pv[i] = ok ? pr[x] : 0.f;
                    tv[i] = ok ? tr[x] : 0.f;
                }
            }
            // u = p + t  -> sums hu (U) and ha (u^2 -> A)
            {
                float k0, k1, k2;
                float su = 0.f, sa = 0.f;
                #pragma unroll
                for (int j = 0; j < 11; ++j) {
                    float u = pv[j + 3] + tv[j + 3];
                    su += u;
                    sa = fmaf(u, u, sa);
                    if (j == 0) k0 = u; else if (j == 1) k1 = u; else if (j == 2) k2 = u;
                }
                hu[0] = su; ha[0] = sa;
                float un;
                un = pv[14] + tv[14]; su += un - k0; sa = fmaf(un, un, sa); sa = fmaf(k0, -k0, sa); hu[1] = su; ha[1] = sa;
                un = pv[15] + tv[15]; su += un - k1; sa = fmaf(un, un, sa); sa = fmaf(k1, -k1, sa); hu[2] = su; ha[2] = sa;
                un = pv[16] + tv[16]; su += un - k2; sa = fmaf(un, un, sa); sa = fmaf(k2, -k2, sa); hu[3] = su; ha[3] = sa;
            }
            // w = p - t  -> sums hw (W) and hb (w^2 -> B)
            {
                float k0, k1, k2;
                float sw = 0.f, sb = 0.f;
                #pragma unroll
                for (int j = 0; j < 11; ++j) {
                    float w = pv[j + 3] - tv[j + 3];
                    sw += w;
                    sb = fmaf(w, w, sb);
                    if (j == 0) k0 = w; else if (j == 1) k1 = w; else if (j == 2) k2 = w;
                }
                hw[0] = sw; hb[0] = sb;
                float wn;
                wn = pv[14] - tv[14]; sw += wn - k0; sb = fmaf(wn, wn, sb); sb = fmaf(k0, -k0, sb); hw[1] = sw; hb[1] = sb;
                wn = pv[15] - tv[15]; sw += wn - k1; sb = fmaf(wn, wn, sb); sb = fmaf(k1, -k1, sb); hw[2] = sw; hb[2] = sb;
                wn = pv[16] - tv[16]; sw += wn - k2; sb = fmaf(wn, wn, sb); sb = fmaf(k2, -k2, sb); hw[3] = sw; hb[3] = sb;
            }
        } else {
            #pragma unroll
            for (int c = 0; c < 4; ++c) { hu[c] = 0.f; hw[c] = 0.f; ha[c] = 0.f; hb[c] = 0.f; }
        }

        float* rowbase = ring + (size_t)wslot * 4 * IMG_W;
        *(float4*)(rowbase + 0 * IMG_W + x0) = make_float4(hu[0], hu[1], hu[2], hu[3]);
        *(float4*)(rowbase + 1 * IMG_W + x0) = make_float4(hw[0], hw[1], hw[2], hw[3]);
        *(float4*)(rowbase + 2 * IMG_W + x0) = make_float4(ha[0], ha[1], ha[2], ha[3]);
        *(float4*)(rowbase + 3 * IMG_W + x0) = make_float4(hb[0], hb[1], hb[2], hb[3]);

        __syncthreads();

        // vertical running sums over the block's columns (stride-128 -> conflict-free)
        const float* addrow = ring + (size_t)wslot * 4 * IMG_W;
        #pragma unroll
        for (int c = 0; c < 4; ++c) {
            int x = tid + 128 * c;
            vU[c] += addrow[0 * IMG_W + x];
            vW[c] += addrow[1 * IMG_W + x];
            vA[c] += addrow[2 * IMG_W + x];
            vB[c] += addrow[3 * IMG_W + x];
        }
        if (k >= 11) {
            const float* subrow = ring + (size_t)sslot * 4 * IMG_W;
            #pragma unroll
            for (int c = 0; c < 4; ++c) {
                int x = tid + 128 * c;
                vU[c] -= subrow[0 * IMG_W + x];
                vW[c] -= subrow[1 * IMG_W + x];
                vA[c] -= subrow[2 * IMG_W + x];
                vB[c] -= subrow[3 * IMG_W + x];
            }
        }

        if (k >= 10) {
            #pragma unroll
            for (int c = 0; c < 4; ++c) {
                float U = vU[c], W = vW[c], A = vA[c], B = vB[c];
                float U2 = U * U;
                float W2 = W * W;
                float d  = U2 - W2;
                float s2 = U2 + W2;
                float e  = A - B;
                float f  = A + B;
                float num1 = fmaf(d, hn2, c1);
                float num2 = fmaf(d, -hn2, fmaf(e, hn1, c2));
                float den1 = fmaf(s2, hn2, c1);
                float sig  = fmaf(s2, -hn2, f * hn1);
                sig = fmaxf(sig, 0.f);
                float den2 = sig + c2;
                float ssim = (num1 * num2) / fmaf(den1, den2, 1e-6f);
                acc += fmaxf(fmaf(ssim, -0.5f, 0.5f), 0.f);
            }
        }

        wslot = (wslot + 1 == SLOTS) ? 0 : wslot + 1;
        sslot = (sslot + 1 == SLOTS) ? 0 : sslot + 1;
    }

    // block reduction of partial loss (reuse ring smem)
    __syncthreads();
    ring[tid] = acc;
    __syncthreads();
    #pragma unroll
    for (int s = 64; s > 0; s >>= 1) {
        if (tid < s) ring[tid] += ring[tid + s];
        __syncthreads();
    }
    if (tid == 0) g_part[bid] = (double)ring[0];
}

// ---------------------------------------------------------------------------
// Kernel 3: deterministic final sum
// ---------------------------------------------------------------------------
__global__ void final_kernel(float* __restrict__ out) {
    int t = threadIdx.x;
    double a = 0.0;
    for (int i = t; i < NBLOCKS; i += 32) a += g_part[i];
    #pragma unroll
    for (int off = 16; off > 0; off >>= 1)
        a += __shfl_down_sync(0xffffffffu, a, off);
    if (t == 0) out[0] = (float)(a / 25165824.0);   // 96 * 512 * 512
}

extern "C" void kernel_launch(void* const* d_in, const int* in_sizes, int n_in,
                              void* d_out, int out_size) {
    (void)in_sizes; (void)n_in; (void)out_size;
    const float* pred   = (const float*)d_in[0];
    const float* target = (const float*)d_in[1];
    float* out = (float*)d_out;

    range_kernel<<<NPLANE, 1024>>>(pred, target);

    const size_t shbytes = (size_t)SLOTS * 4 * IMG_W * sizeof(float);  // 106496 B
    cudaFuncSetAttribute(ssim_kernel, cudaFuncAttributeMaxDynamicSharedMemorySize, (int)shbytes);
    ssim_kernel<<<NBLOCKS, TPB, shbytes>>>(pred, target);

    final_kernel<<<1, 32>>>(out);
}

// round 2
// speedup vs baseline: 1.4026x; 1.4026x over previous
#include <cuda_runtime.h>

#define NPLANE 96
#define IMG_H 512
#define IMG_W 512
#define PLANE (IMG_H * IMG_W)
#define NSTRIP 3
#define NBLOCKS (NPLANE * NSTRIP)
#define TPB 128
#define SLOTS 12
#define INB_W 528                      // 8 zero + 512 data + 8 zero
#define RING_FLOATS (SLOTS * 4 * IMG_W)
#define INB_FLOATS (2 * 2 * INB_W)
#define SMEM_BYTES ((RING_FLOATS + INB_FLOATS) * 4)

__device__ float  g_c1[NPLANE];
__device__ float  g_c2[NPLANE];
__device__ float  g_pmax[NPLANE * 4];
__device__ float  g_pmin[NPLANE * 4];
__device__ double g_part[NBLOCKS];

// ---------------------------------------------------------------------------
// Kernel 1a: per-quarter-plane min/max partials (384 blocks -> full chip)
// ---------------------------------------------------------------------------
__global__ void __launch_bounds__(256) range_part(const float* __restrict__ pred,
                                                  const float* __restrict__ target) {
    __shared__ float sx[256];
    __shared__ float sn[256];
    const int plane = blockIdx.x >> 2;
    const int quad  = blockIdx.x & 3;
    const float4* __restrict__ P = (const float4*)(pred   + (size_t)plane * PLANE) + (size_t)quad * 16384;
    const float4* __restrict__ T = (const float4*)(target + (size_t)plane * PLANE) + (size_t)quad * 16384;
    float mx = -1e30f, mn = 1e30f;
    #pragma unroll 4
    for (int i = threadIdx.x; i < 16384; i += 256) {
        float4 a = __ldg(P + i);
        float4 b = __ldg(T + i);
        float lmx = fmaxf(fmaxf(fmaxf(a.x, b.x), fmaxf(a.y, b.y)),
                          fmaxf(fmaxf(a.z, b.z), fmaxf(a.w, b.w)));
        float lmn = fminf(fminf(fminf(a.x, b.x), fminf(a.y, b.y)),
                          fminf(fminf(a.z, b.z), fminf(a.w, b.w)));
        mx = fmaxf(mx, lmx);
        mn = fminf(mn, lmn);
    }
    sx[threadIdx.x] = mx;
    sn[threadIdx.x] = mn;
    __syncthreads();
    for (int s = 128; s > 0; s >>= 1) {
        if (threadIdx.x < s) {
            sx[threadIdx.x] = fmaxf(sx[threadIdx.x], sx[threadIdx.x + s]);
            sn[threadIdx.x] = fminf(sn[threadIdx.x], sn[threadIdx.x + s]);
        }
        __syncthreads();
    }
    if (threadIdx.x == 0) {
        g_pmax[blockIdx.x] = sx[0];
        g_pmin[blockIdx.x] = sn[0];
    }
}

// ---------------------------------------------------------------------------
// Kernel 1b: combine partials -> c1, c2 per plane
// ---------------------------------------------------------------------------
__global__ void range_combine() {
    const int t = threadIdx.x;
    if (t < NPLANE) {
        float mx = fmaxf(fmaxf(g_pmax[4 * t], g_pmax[4 * t + 1]),
                         fmaxf(g_pmax[4 * t + 2], g_pmax[4 * t + 3]));
        float mn = fminf(fminf(g_pmin[4 * t], g_pmin[4 * t + 1]),
                         fminf(g_pmin[4 * t + 2], g_pmin[4 * t + 3]));
        float dr = fmaxf(mx - mn, 1e-6f);
        float a = 0.01f * dr;
        float b = 0.03f * dr;
        g_c1[t] = a * a;
        g_c2[t] = b * b;
    }
}

// ---------------------------------------------------------------------------
// Kernel 2: pipelined fused separable box SSIM
//   thread t owns columns 4t..4t+3 for horizontal AND vertical.
//   per row: prefetch LDG (next row) | stage u,w -> smem | horizontal from
//   smem (prev row) | vertical add from regs | sub from 12-slot ring | epilogue
// ---------------------------------------------------------------------------
__global__ void __launch_bounds__(TPB, 2) ssim_kernel(const float* __restrict__ pred,
                                                      const float* __restrict__ target) {
    extern __shared__ float smem[];
    float* ring  = smem;                 // [SLOTS][4][512]
    float* inbuf = smem + RING_FLOATS;   // [2][2][INB_W]

    const int bid   = blockIdx.x;
    const int plane = bid / NSTRIP;
    const int strip = bid - plane * NSTRIP;
    const int y0    = strip * 171;
    const int R     = (strip == 2) ? 170 : 171;
    const int KMAX  = R + 10;

    const float* __restrict__ P = pred   + (size_t)plane * PLANE;
    const float* __restrict__ T = target + (size_t)plane * PLANE;
    const float c1 = g_c1[plane];
    const float c2 = g_c2[plane];

    const int tid = threadIdx.x;
    const int x0  = tid * 4;

    // zero inbuf (pads must be zero; data region overwritten every row)
    for (int z = tid; z < INB_FLOATS; z += TPB) inbuf[z] = 0.f;

    // prefetch first input row (iy = y0 - 5)
    float4 pp, tt;
    {
        int iy = y0 - 5;
        if (iy >= 0) {
            pp = __ldg((const float4*)(P + (size_t)iy * IMG_W + x0));
            tt = __ldg((const float4*)(T + (size_t)iy * IMG_W + x0));
        } else {
            pp = make_float4(0.f, 0.f, 0.f, 0.f);
            tt = make_float4(0.f, 0.f, 0.f, 0.f);
        }
    }

    float vU[4] = {0.f, 0.f, 0.f, 0.f};
    float vW[4] = {0.f, 0.f, 0.f, 0.f};
    float vA[4] = {0.f, 0.f, 0.f, 0.f};
    float vB[4] = {0.f, 0.f, 0.f, 0.f};
    float acc = 0.f;

    const float hn1 = 0.5f / 121.0f;
    const float hn2 = 0.5f / (121.0f * 121.0f);

    int wslot = 0;  // = r % SLOTS

    for (int i = 0; i <= KMAX; ++i) {
        __syncthreads();

        // --- stage row i (u,w) from prefetched regs; prefetch row i+1 ---
        if (i < KMAX) {
            float* ib = inbuf + (size_t)(i & 1) * 2 * INB_W;
            *(float4*)(ib + 8 + x0) =
                make_float4(pp.x + tt.x, pp.y + tt.y, pp.z + tt.z, pp.w + tt.w);
            *(float4*)(ib + INB_W + 8 + x0) =
                make_float4(pp.x - tt.x, pp.y - tt.y, pp.z - tt.z, pp.w - tt.w);

            int iy = y0 - 4 + i;  // input row for stage i+1
            if (i + 1 < KMAX && iy >= 0 && iy < IMG_H) {
                pp = __ldg((const float4*)(P + (size_t)iy * IMG_W + x0));
                tt = __ldg((const float4*)(T + (size_t)iy * IMG_W + x0));
            } else {
                pp = make_float4(0.f, 0.f, 0.f, 0.f);
                tt = make_float4(0.f, 0.f, 0.f, 0.f);
            }
        }

        // --- horizontal + vertical + epilogue for h-row r = i-1 ---
        if (i >= 1) {
            const int r = i - 1;
            const float* ib = inbuf + (size_t)(r & 1) * 2 * INB_W;

            float hu[4], ha[4], hw[4], hb[4];
            {   // u quantities: stored idx base = 8 + (4t-8) = x0
                float v[20];
                #pragma unroll
                for (int j = 0; j < 5; ++j)
                    *(float4*)(v + 4 * j) = *(const float4*)(ib + x0 + 4 * j);
                float s = 0.f, q = 0.f;
                #pragma unroll
                for (int j = 3; j < 14; ++j) { s += v[j]; q = fmaf(v[j], v[j], q); }
                hu[0] = s; ha[0] = q;
                #pragma unroll
                for (int m = 0; m < 3; ++m) {
                    float a = v[14 + m], b = v[3 + m];
                    s += a - b;
                    q = fmaf(a, a, q);
                    q = fmaf(b, -b, q);
                    hu[m + 1] = s; ha[m + 1] = q;
                }
            }
            {   // w quantities
                const float* ibw = ib + INB_W;
                float v[20];
                #pragma unroll
                for (int j = 0; j < 5; ++j)
                    *(float4*)(v + 4 * j) = *(const float4*)(ibw + x0 + 4 * j);
                float s = 0.f, q = 0.f;
                #pragma unroll
                for (int j = 3; j < 14; ++j) { s += v[j]; q = fmaf(v[j], v[j], q); }
                hw[0] = s; hb[0] = q;
                #pragma unroll
                for (int m = 0; m < 3; ++m) {
                    float a = v[14 + m], b = v[3 + m];
                    s += a - b;
                    q = fmaf(a, a, q);
                    q = fmaf(b, -b, q);
                    hw[m + 1] = s; hb[m + 1] = q;
                }
            }

            // vertical add straight from registers
            #pragma unroll
            for (int c = 0; c < 4; ++c) {
                vU[c] += hu[c]; vW[c] += hw[c]; vA[c] += ha[c]; vB[c] += hb[c];
            }

            // ring write (needed for subtraction 11 rows later)
            float* rw = ring + (size_t)wslot * 4 * IMG_W + x0;
            *(float4*)(rw)             = make_float4(hu[0], hu[1], hu[2], hu[3]);
            *(float4*)(rw + IMG_W)     = make_float4(hw[0], hw[1], hw[2], hw[3]);
            *(float4*)(rw + 2 * IMG_W) = make_float4(ha[0], ha[1], ha[2], ha[3]);
            *(float4*)(rw + 3 * IMG_W) = make_float4(hb[0], hb[1], hb[2], hb[3]);

            // subtract h-row r-11 (slot = (r-11) % 12 == wslot+1 mod 12)
            if (r >= 11) {
                int ss = wslot + 1; if (ss == SLOTS) ss = 0;
                const float* rs = ring + (size_t)ss * 4 * IMG_W + x0;
                float4 su = *(const float4*)(rs);
                float4 sw = *(const float4*)(rs + IMG_W);
                float4 sa = *(const float4*)(rs + 2 * IMG_W);
                float4 sb = *(const float4*)(rs + 3 * IMG_W);
                vU[0] -= su.x; vU[1] -= su.y; vU[2] -= su.z; vU[3] -= su.w;
                vW[0] -= sw.x; vW[1] -= sw.y; vW[2] -= sw.z; vW[3] -= sw.w;
                vA[0] -= sa.x; vA[1] -= sa.y; vA[2] -= sa.z; vA[3] -= sa.w;
                vB[0] -= sb.x; vB[1] -= sb.y; vB[2] -= sb.z; vB[3] -= sb.w;
            }

            // epilogue for output row r-10
            if (r >= 10) {
                #pragma unroll
                for (int c = 0; c < 4; ++c) {
                    float U = vU[c], W = vW[c], A = vA[c], B = vB[c];
                    float U2 = U * U;
                    float W2 = W * W;
                    float d  = U2 - W2;
                    float s2 = U2 + W2;
                    float e  = A - B;
                    float f  = A + B;
                    float num1 = fmaf(d, hn2, c1);
                    float num2 = fmaf(d, -hn2, fmaf(e, hn1, c2));
                    float den1 = fmaf(s2, hn2, c1);
                    float sig  = fmaf(s2, -hn2, f * hn1);
                    sig = fmaxf(sig, 0.f);
                    float den2 = sig + c2;
                    float ssim = (num1 * num2) / fmaf(den1, den2, 1e-6f);
                    acc += fmaxf(fmaf(ssim, -0.5f, 0.5f), 0.f);
                }
            }

            wslot++; if (wslot == SLOTS) wslot = 0;
        }
    }

    // block reduction (reuse smem)
    __syncthreads();
    smem[tid] = acc;
    __syncthreads();
    #pragma unroll
    for (int s = 64; s > 0; s >>= 1) {
        if (tid < s) smem[tid] += smem[tid + s];
        __syncthreads();
    }
    if (tid == 0) g_part[bid] = (double)smem[0];
}

// ---------------------------------------------------------------------------
// Kernel 3: deterministic final sum
// ---------------------------------------------------------------------------
__global__ void final_kernel(float* __restrict__ out) {
    int t = threadIdx.x;
    double a = 0.0;
    for (int i = t; i < NBLOCKS; i += 32) a += g_part[i];
    #pragma unroll
    for (int off = 16; off > 0; off >>= 1)
        a += __shfl_down_sync(0xffffffffu, a, off);
    if (t == 0) out[0] = (float)(a / 25165824.0);   // 96 * 512 * 512
}

extern "C" void kernel_launch(void* const* d_in, const int* in_sizes, int n_in,
                              void* d_out, int out_size) {
    (void)in_sizes; (void)n_in; (void)out_size;
    const float* pred   = (const float*)d_in[0];
    const float* target = (const float*)d_in[1];
    float* out = (float*)d_out;

    range_part<<<NPLANE * 4, 256>>>(pred, target);
    range_combine<<<1, 128>>>();

    cudaFuncSetAttribute(ssim_kernel, cudaFuncAttributeMaxDynamicSharedMemorySize, SMEM_BYTES);
    ssim_kernel<<<NBLOCKS, TPB, SMEM_BYTES>>>(pred, target);

    final_kernel<<<1, 32>>>(out);
}

// round 3
// speedup vs baseline: 1.6029x; 1.1428x over previous
#include <cuda_runtime.h>

#define NPLANE 96
#define IMG_H 512
#define IMG_W 512
#define PLANE (IMG_H * IMG_W)
#define NSTRIP 3
#define NBLOCKS (NPLANE * NSTRIP)
#define TPB 128
#define SLOTS 12
#define INB2 528                         // padded row width in {u,w} float2 entries
#define RING_ULL (SLOTS * 2 * IMG_W)     // [slot][{UW,AB}][512]
#define SMEM_ULL (RING_ULL + 2 * INB2)
#define SMEM_BYTES (SMEM_ULL * 8)

typedef unsigned long long ull;

__device__ float        g_pmax[NPLANE * 4];
__device__ float        g_pmin[NPLANE * 4];
__device__ double       g_part[NBLOCKS];
__device__ unsigned int g_ticket = 0;

// ---------------- f32x2 packed helpers ----------------
__device__ __forceinline__ ull f2add(ull a, ull b) {
    ull d; asm("add.rn.f32x2 %0,%1,%2;" : "=l"(d) : "l"(a), "l"(b)); return d;
}
__device__ __forceinline__ ull f2mul(ull a, ull b) {
    ull d; asm("mul.rn.f32x2 %0,%1,%2;" : "=l"(d) : "l"(a), "l"(b)); return d;
}
__device__ __forceinline__ ull f2fma(ull a, ull b, ull c) {
    ull d; asm("fma.rn.f32x2 %0,%1,%2,%3;" : "=l"(d) : "l"(a), "l"(b), "l"(c)); return d;
}
__device__ __forceinline__ ull f2pk(float x, float y) {
    ull d; asm("mov.b64 %0,{%1,%2};" : "=l"(d) : "f"(x), "f"(y)); return d;
}
__device__ __forceinline__ void f2up(ull s, float& x, float& y) {
    asm("mov.b64 {%0,%1},%2;" : "=f"(x), "=f"(y) : "l"(s));
}

// ---------------------------------------------------------------------------
// Kernel 1: per-quarter-plane min/max partials (384 blocks)
// ---------------------------------------------------------------------------
__global__ void __launch_bounds__(256) range_part(const float* __restrict__ pred,
                                                  const float* __restrict__ target) {
    __shared__ float sx[256];
    __shared__ float sn[256];
    const int plane = blockIdx.x >> 2;
    const int quad  = blockIdx.x & 3;
    const float4* __restrict__ P = (const float4*)(pred   + (size_t)plane * PLANE) + (size_t)quad * 16384;
    const float4* __restrict__ T = (const float4*)(target + (size_t)plane * PLANE) + (size_t)quad * 16384;
    float mx = -1e30f, mn = 1e30f;
    #pragma unroll 4
    for (int i = threadIdx.x; i < 16384; i += 256) {
        float4 a = __ldg(P + i);
        float4 b = __ldg(T + i);
        float lmx = fmaxf(fmaxf(fmaxf(a.x, b.x), fmaxf(a.y, b.y)),
                          fmaxf(fmaxf(a.z, b.z), fmaxf(a.w, b.w)));
        float lmn = fminf(fminf(fminf(a.x, b.x), fminf(a.y, b.y)),
                          fminf(fminf(a.z, b.z), fminf(a.w, b.w)));
        mx = fmaxf(mx, lmx);
        mn = fminf(mn, lmn);
    }
    sx[threadIdx.x] = mx;
    sn[threadIdx.x] = mn;
    __syncthreads();
    for (int s = 128; s > 0; s >>= 1) {
        if (threadIdx.x < s) {
            sx[threadIdx.x] = fmaxf(sx[threadIdx.x], sx[threadIdx.x + s]);
            sn[threadIdx.x] = fminf(sn[threadIdx.x], sn[threadIdx.x + s]);
        }
        __syncthreads();
    }
    if (threadIdx.x == 0) {
        g_pmax[blockIdx.x] = sx[0];
        g_pmin[blockIdx.x] = sn[0];
    }
}

// ---------------------------------------------------------------------------
// Kernel 2: fused separable box SSIM, f32x2-packed {u,w}/{A,B} datapath.
//   Ends with a last-block-done global reduction writing the scalar output.
// ---------------------------------------------------------------------------
__global__ void __launch_bounds__(TPB, 2) ssim_kernel(const float* __restrict__ pred,
                                                      const float* __restrict__ target,
                                                      float* __restrict__ out) {
    extern __shared__ ull smem_u[];
    ull* ring  = smem_u;                 // [SLOTS][2][512] : {U,W} then {A,B}
    ull* inbuf = smem_u + RING_ULL;      // [2][INB2]       : {u,w} entries
    __shared__ int s_last;

    const int bid   = blockIdx.x;
    const int plane = bid / NSTRIP;
    const int strip = bid - plane * NSTRIP;
    const int y0    = strip * 171;
    const int R     = (strip == 2) ? 170 : 171;
    const int KMAX  = R + 10;

    const float* __restrict__ P = pred   + (size_t)plane * PLANE;
    const float* __restrict__ T = target + (size_t)plane * PLANE;

    // per-plane constants from range partials
    const int pb = plane * 4;
    float mx = fmaxf(fmaxf(g_pmax[pb], g_pmax[pb + 1]), fmaxf(g_pmax[pb + 2], g_pmax[pb + 3]));
    float mn = fminf(fminf(g_pmin[pb], g_pmin[pb + 1]), fminf(g_pmin[pb + 2], g_pmin[pb + 3]));
    float dr = fmaxf(mx - mn, 1e-6f);
    const float c1 = (0.01f * dr) * (0.01f * dr);
    const float c2 = (0.03f * dr) * (0.03f * dr);

    const int tid = threadIdx.x;
    const int x0  = tid * 4;

    // zero staging buffers (pads must be zero)
    for (int z = tid; z < 2 * INB2; z += TPB) inbuf[z] = 0ull;

    // prefetch first input row
    float4 pp, tt;
    {
        int iy = y0 - 5;
        if (iy >= 0) {
            pp = __ldg((const float4*)(P + (size_t)iy * IMG_W + x0));
            tt = __ldg((const float4*)(T + (size_t)iy * IMG_W + x0));
        } else {
            pp = make_float4(0.f, 0.f, 0.f, 0.f);
            tt = make_float4(0.f, 0.f, 0.f, 0.f);
        }
    }

    const ull NEG1 = f2pk(-1.f, -1.f);
    ull vUW[4] = {0ull, 0ull, 0ull, 0ull};
    ull vAB[4] = {0ull, 0ull, 0ull, 0ull};
    float acc = 0.f;

    const float hn1  = 0.5f / 121.0f;
    const float hn2  = 0.5f / (121.0f * 121.0f);
    const float nhn2 = -hn2;

    int wslot = 0;

    for (int i = 0; i <= KMAX; ++i) {
        __syncthreads();

        // --- stage row i as {u,w} entries; prefetch row i+1 ---
        if (i < KMAX) {
            float* ib = (float*)(inbuf + (size_t)(i & 1) * INB2);
            // entries 8+x0 .. 8+x0+3 ; each entry = {u,w}
            *(float4*)(ib + 2 * (8 + x0)) =
                make_float4(pp.x + tt.x, pp.x - tt.x, pp.y + tt.y, pp.y - tt.y);
            *(float4*)(ib + 2 * (8 + x0) + 4) =
                make_float4(pp.z + tt.z, pp.z - tt.z, pp.w + tt.w, pp.w - tt.w);

            int iy = y0 - 4 + i;
            if (i + 1 < KMAX && iy >= 0 && iy < IMG_H) {
                pp = __ldg((const float4*)(P + (size_t)iy * IMG_W + x0));
                tt = __ldg((const float4*)(T + (size_t)iy * IMG_W + x0));
            } else {
                pp = make_float4(0.f, 0.f, 0.f, 0.f);
                tt = make_float4(0.f, 0.f, 0.f, 0.f);
            }
        }

        // --- process h-row r = i-1 ---
        if (i >= 1) {
            const int r = i - 1;
            const ull* ib = inbuf + (size_t)(r & 1) * INB2;

            // load packed window: entries x0-6 .. x0+9  (buffer idx x0+2 .. x0+17)
            ull v[16];
            #pragma unroll
            for (int j = 0; j < 8; ++j) {
                ulonglong2 q = *(const ulonglong2*)(ib + x0 + 2 + 2 * j);
                v[2 * j]     = q.x;
                v[2 * j + 1] = q.y;
            }

            // initial window: entries v[1..11]  ({U,W} sum, {A,B} sq-sum)
            ull h[4], g[4];
            {
                ull s01 = f2add(v[1], v[2]);
                ull s23 = f2add(v[3], v[4]);
                ull s45 = f2add(v[5], v[6]);
                ull s67 = f2add(v[7], v[8]);
                ull s89 = f2add(v[9], v[10]);
                ull sA  = f2add(s01, s23);
                ull sB  = f2add(s45, s67);
                ull sC  = f2add(s89, v[11]);
                ull suw = f2add(f2add(sA, sB), sC);

                ull qa = f2mul(v[1], v[1]);
                qa = f2fma(v[2], v[2], qa);
                qa = f2fma(v[3], v[3], qa);
                qa = f2fma(v[4], v[4], qa);
                qa = f2fma(v[5], v[5], qa);
                qa = f2fma(v[6], v[6], qa);
                ull qb = f2mul(v[7], v[7]);
                qb = f2fma(v[8], v[8], qb);
                qb = f2fma(v[9], v[9], qb);
                qb = f2fma(v[10], v[10], qb);
                qb = f2fma(v[11], v[11], qb);
                ull qab = f2add(qa, qb);

                h[0] = suw; g[0] = qab;
                #pragma unroll
                for (int m = 0; m < 3; ++m) {
                    ull vn = v[12 + m];
                    ull vo = v[1 + m];
                    suw = f2add(suw, vn);
                    suw = f2fma(vo, NEG1, suw);
                    qab = f2fma(vn, vn, qab);
                    ull von = f2mul(vo, NEG1);
                    qab = f2fma(vo, von, qab);
                    h[m + 1] = suw; g[m + 1] = qab;
                }
            }

            // vertical add (registers)
            #pragma unroll
            for (int c = 0; c < 4; ++c) {
                vUW[c] = f2add(vUW[c], h[c]);
                vAB[c] = f2add(vAB[c], g[c]);
            }

            // ring write
            ull* rw = ring + (size_t)wslot * (2 * IMG_W) + x0;
            *(ulonglong2*)(rw)               = make_ulonglong2(h[0], h[1]);
            *(ulonglong2*)(rw + 2)           = make_ulonglong2(h[2], h[3]);
            *(ulonglong2*)(rw + IMG_W)       = make_ulonglong2(g[0], g[1]);
            *(ulonglong2*)(rw + IMG_W + 2)   = make_ulonglong2(g[2], g[3]);

            // subtract row r-11
            if (r >= 11) {
                int ss = wslot + 1; if (ss == SLOTS) ss = 0;
                const ull* rs = ring + (size_t)ss * (2 * IMG_W) + x0;
                ulonglong2 a0 = *(const ulonglong2*)(rs);
                ulonglong2 a1 = *(const ulonglong2*)(rs + 2);
                ulonglong2 b0 = *(const ulonglong2*)(rs + IMG_W);
                ulonglong2 b1 = *(const ulonglong2*)(rs + IMG_W + 2);
                vUW[0] = f2fma(a0.x, NEG1, vUW[0]);
                vUW[1] = f2fma(a0.y, NEG1, vUW[1]);
                vUW[2] = f2fma(a1.x, NEG1, vUW[2]);
                vUW[3] = f2fma(a1.y, NEG1, vUW[3]);
                vAB[0] = f2fma(b0.x, NEG1, vAB[0]);
                vAB[1] = f2fma(b0.y, NEG1, vAB[1]);
                vAB[2] = f2fma(b1.x, NEG1, vAB[2]);
                vAB[3] = f2fma(b1.y, NEG1, vAB[3]);
            }

            // epilogue for output row r-10
            if (r >= 10) {
                #pragma unroll
                for (int c = 0; c < 4; ++c) {
                    float U, W, A, B;
                    ull sq = f2mul(vUW[c], vUW[c]);
                    float U2, W2;
                    f2up(sq, U2, W2);
                    f2up(vAB[c], A, B);
                    float d  = U2 - W2;
                    float s2 = U2 + W2;
                    float e  = A - B;
                    float f  = A + B;
                    float num1 = fmaf(d, hn2, c1);
                    float num2 = fmaf(d, nhn2, fmaf(e, hn1, c2));
                    float den1 = fmaf(s2, hn2, c1);
                    float sig  = fmaf(s2, nhn2, f * hn1);
                    sig = fmaxf(sig, 0.f);
                    float den = fmaf(den1, sig + c2, 1e-6f);
                    float ssim = __fdividef(num1 * num2, den);
                    acc += fmaxf(fmaf(ssim, -0.5f, 0.5f), 0.f);
                    (void)U; (void)W;
                }
            }

            wslot++; if (wslot == SLOTS) wslot = 0;
        }
    }

    // block reduction (reuse smem as float scratch)
    __syncthreads();
    float* red = (float*)smem_u;
    red[tid] = acc;
    __syncthreads();
    #pragma unroll
    for (int s = 64; s > 0; s >>= 1) {
        if (tid < s) red[tid] += red[tid + s];
        __syncthreads();
    }

    if (tid == 0) {
        g_part[bid] = (double)red[0];
        __threadfence();
        unsigned int t = atomicAdd(&g_ticket, 1u);
        s_last = (t == NBLOCKS - 1) ? 1 : 0;
    }
    __syncthreads();

    if (s_last) {
        __threadfence();
        double a = 0.0;
        for (int i = tid; i < NBLOCKS; i += TPB) a += g_part[i];
        double* dred = (double*)smem_u;
        dred[tid] = a;
        __syncthreads();
        #pragma unroll
        for (int s = 64; s > 0; s >>= 1) {
            if (tid < s) dred[tid] += dred[tid + s];
            __syncthreads();
        }
        if (tid == 0) {
            out[0] = (float)(dred[0] / 25165824.0);   // 96*512*512
            g_ticket = 0;                              // reset for next replay
        }
    }
}

extern "C" void kernel_launch(void* const* d_in, const int* in_sizes, int n_in,
                              void* d_out, int out_size) {
    (void)in_sizes; (void)n_in; (void)out_size;
    const float* pred   = (const float*)d_in[0];
    const float* target = (const float*)d_in[1];
    float* out = (float*)d_out;

    range_part<<<NPLANE * 4, 256>>>(pred, target);

    cudaFuncSetAttribute(ssim_kernel, cudaFuncAttributeMaxDynamicSharedMemorySize, SMEM_BYTES);
    ssim_kernel<<<NBLOCKS, TPB, SMEM_BYTES>>>(pred, target, out);
}

// round 4
// speedup vs baseline: 1.8241x; 1.1380x over previous
#include <cuda_runtime.h>

#define NPLANE 96
#define IMG_H 512
#define IMG_W 512
#define PLANE (IMG_H * IMG_W)
#define NSTRIP 3
#define NBLOCKS (NPLANE * NSTRIP)
#define TPB 128
#define SLOTS 12
// staged row: 2 half-arrays (E,O) x 132 ulonglong2 (halo 2 groups each side)
#define INB_ULL (2 * 132 * 2)            // per buffer, in ull units (=528)
#define RING_ULL (SLOTS * 2 * IMG_W)     // [slot][{UW,AB}][512 ull split-half]
#define SMEM_ULL (RING_ULL + 2 * INB_ULL)
#define SMEM_BYTES (SMEM_ULL * 8)

typedef unsigned long long ull;

__device__ float        g_pmax[NPLANE * 4];
__device__ float        g_pmin[NPLANE * 4];
__device__ double       g_part[NBLOCKS];
__device__ unsigned int g_ticket = 0;

// ---------------- f32x2 packed helpers ----------------
__device__ __forceinline__ ull f2add(ull a, ull b) {
    ull d; asm("add.rn.f32x2 %0,%1,%2;" : "=l"(d) : "l"(a), "l"(b)); return d;
}
__device__ __forceinline__ ull f2mul(ull a, ull b) {
    ull d; asm("mul.rn.f32x2 %0,%1,%2;" : "=l"(d) : "l"(a), "l"(b)); return d;
}
__device__ __forceinline__ ull f2fma(ull a, ull b, ull c) {
    ull d; asm("fma.rn.f32x2 %0,%1,%2,%3;" : "=l"(d) : "l"(a), "l"(b), "l"(c)); return d;
}
__device__ __forceinline__ ull f2pk(float x, float y) {
    ull d; asm("mov.b64 %0,{%1,%2};" : "=l"(d) : "f"(x), "f"(y)); return d;
}
__device__ __forceinline__ void f2up(ull s, float& x, float& y) {
    asm("mov.b64 {%0,%1},%2;" : "=f"(x), "=f"(y) : "l"(s));
}

// ---------------------------------------------------------------------------
// Kernel 1: per-quarter-plane min/max partials (384 blocks)
// ---------------------------------------------------------------------------
__global__ void __launch_bounds__(256) range_part(const float* __restrict__ pred,
                                                  const float* __restrict__ target) {
    __shared__ float sx[256];
    __shared__ float sn[256];
    const int plane = blockIdx.x >> 2;
    const int quad  = blockIdx.x & 3;
    const float4* __restrict__ P = (const float4*)(pred   + (size_t)plane * PLANE) + (size_t)quad * 16384;
    const float4* __restrict__ T = (const float4*)(target + (size_t)plane * PLANE) + (size_t)quad * 16384;
    float mx = -1e30f, mn = 1e30f;
    #pragma unroll 4
    for (int i = threadIdx.x; i < 16384; i += 256) {
        float4 a = __ldg(P + i);
        float4 b = __ldg(T + i);
        float lmx = fmaxf(fmaxf(fmaxf(a.x, b.x), fmaxf(a.y, b.y)),
                          fmaxf(fmaxf(a.z, b.z), fmaxf(a.w, b.w)));
        float lmn = fminf(fminf(fminf(a.x, b.x), fminf(a.y, b.y)),
                          fminf(fminf(a.z, b.z), fminf(a.w, b.w)));
        mx = fmaxf(mx, lmx);
        mn = fminf(mn, lmn);
    }
    sx[threadIdx.x] = mx;
    sn[threadIdx.x] = mn;
    __syncthreads();
    for (int s = 128; s > 0; s >>= 1) {
        if (threadIdx.x < s) {
            sx[threadIdx.x] = fmaxf(sx[threadIdx.x], sx[threadIdx.x + s]);
            sn[threadIdx.x] = fminf(sn[threadIdx.x], sn[threadIdx.x + s]);
        }
        __syncthreads();
    }
    if (threadIdx.x == 0) {
        g_pmax[blockIdx.x] = sx[0];
        g_pmin[blockIdx.x] = sn[0];
    }
}

// ---------------------------------------------------------------------------
// Kernel 2: fused separable box SSIM, f32x2 datapath, split-half smem layout
//   (all LDS/STS are 16B-per-lane stride -> bank-conflict-free)
// ---------------------------------------------------------------------------
__global__ void __launch_bounds__(TPB, 2) ssim_kernel(const float* __restrict__ pred,
                                                      const float* __restrict__ target,
                                                      float* __restrict__ out) {
    extern __shared__ ull smem_u[];
    ull* ring  = smem_u;                 // SLOTS x { UW[512], AB[512] } split-half
    ull* inbuf = smem_u + RING_ULL;      // 2 x { E[132], O[132] } of ulonglong2
    __shared__ int s_last;

    const int bid   = blockIdx.x;
    const int plane = bid / NSTRIP;
    const int strip = bid - plane * NSTRIP;
    const int y0    = strip * 171;
    const int R     = (strip == 2) ? 170 : 171;
    const int KMAX  = R + 10;

    const float* __restrict__ P = pred   + (size_t)plane * PLANE;
    const float* __restrict__ T = target + (size_t)plane * PLANE;

    // per-plane constants from range partials
    const int pb = plane * 4;
    float mx = fmaxf(fmaxf(g_pmax[pb], g_pmax[pb + 1]), fmaxf(g_pmax[pb + 2], g_pmax[pb + 3]));
    float mn = fminf(fminf(g_pmin[pb], g_pmin[pb + 1]), fminf(g_pmin[pb + 2], g_pmin[pb + 3]));
    float dr = fmaxf(mx - mn, 1e-6f);
    const float c1 = (0.01f * dr) * (0.01f * dr);
    const float c2 = (0.03f * dr) * (0.03f * dr);

    const int tid = threadIdx.x;
    const int x0  = tid * 4;

    // zero staging buffers (halo groups must stay zero)
    for (int z = tid; z < 2 * INB_ULL; z += TPB) inbuf[z] = 0ull;

    // prefetch first input row
    float4 pp, tt;
    {
        int iy = y0 - 5;
        if (iy >= 0) {
            pp = __ldg((const float4*)(P + (size_t)iy * IMG_W + x0));
            tt = __ldg((const float4*)(T + (size_t)iy * IMG_W + x0));
        } else {
            pp = make_float4(0.f, 0.f, 0.f, 0.f);
            tt = make_float4(0.f, 0.f, 0.f, 0.f);
        }
    }

    const ull NEG1 = f2pk(-1.f, -1.f);
    ull vUW[4] = {0ull, 0ull, 0ull, 0ull};
    ull vAB[4] = {0ull, 0ull, 0ull, 0ull};
    float acc = 0.f;

    const float hn1  = 0.5f / 121.0f;
    const float hn2  = 0.5f / (121.0f * 121.0f);
    const float nhn2 = -hn2;

    int wslot = 0;

    for (int i = 0; i <= KMAX; ++i) {
        __syncthreads();

        // --- stage row i as split-half {u,w} pairs; prefetch row i+1 ---
        if (i < KMAX) {
            ull* Eb = inbuf + (size_t)(i & 1) * INB_ULL;   // E half (132 ulonglong2)
            ull* Ob = Eb + 264;                            // O half
            // E_t = cols {4t, 4t+1}
            *(float4*)(Eb + (tid + 2) * 2) =
                make_float4(pp.x + tt.x, pp.x - tt.x, pp.y + tt.y, pp.y - tt.y);
            // O_t = cols {4t+2, 4t+3}
            *(float4*)(Ob + (tid + 2) * 2) =
                make_float4(pp.z + tt.z, pp.z - tt.z, pp.w + tt.w, pp.w - tt.w);

            int iy = y0 - 4 + i;
            if (i + 1 < KMAX && iy >= 0 && iy < IMG_H) {
                pp = __ldg((const float4*)(P + (size_t)iy * IMG_W + x0));
                tt = __ldg((const float4*)(T + (size_t)iy * IMG_W + x0));
            } else {
                pp = make_float4(0.f, 0.f, 0.f, 0.f);
                tt = make_float4(0.f, 0.f, 0.f, 0.f);
            }
        }

        // --- process h-row r = i-1 ---
        if (i >= 1) {
            const int r = i - 1;
            const ull* Eb = inbuf + (size_t)(r & 1) * INB_ULL;
            const ull* Ob = Eb + 264;

            // window entries 4t-6 .. 4t+9 -> v[0..15], all conflict-free 16B loads
            ull v[16];
            {
                ulonglong2 q;
                q = *(const ulonglong2*)(Ob + tid * 2);           v[0]  = q.x; v[1]  = q.y; // O_{t-2}
                q = *(const ulonglong2*)(Eb + (tid + 1) * 2);     v[2]  = q.x; v[3]  = q.y; // E_{t-1}
                q = *(const ulonglong2*)(Ob + (tid + 1) * 2);     v[4]  = q.x; v[5]  = q.y; // O_{t-1}
                q = *(const ulonglong2*)(Eb + (tid + 2) * 2);     v[6]  = q.x; v[7]  = q.y; // E_t
                q = *(const ulonglong2*)(Ob + (tid + 2) * 2);     v[8]  = q.x; v[9]  = q.y; // O_t
                q = *(const ulonglong2*)(Eb + (tid + 3) * 2);     v[10] = q.x; v[11] = q.y; // E_{t+1}
                q = *(const ulonglong2*)(Ob + (tid + 3) * 2);     v[12] = q.x; v[13] = q.y; // O_{t+1}
                q = *(const ulonglong2*)(Eb + (tid + 4) * 2);     v[14] = q.x; v[15] = q.y; // E_{t+2}
            }

            // initial window: entries v[1..11]  ({U,W} sum, {A,B} sq-sum)
            ull h[4], g[4];
            {
                ull s01 = f2add(v[1], v[2]);
                ull s23 = f2add(v[3], v[4]);
                ull s45 = f2add(v[5], v[6]);
                ull s67 = f2add(v[7], v[8]);
                ull s89 = f2add(v[9], v[10]);
                ull sA  = f2add(s01, s23);
                ull sB  = f2add(s45, s67);
                ull sC  = f2add(s89, v[11]);
                ull suw = f2add(f2add(sA, sB), sC);

                ull qa = f2mul(v[1], v[1]);
                qa = f2fma(v[2], v[2], qa);
                qa = f2fma(v[3], v[3], qa);
                qa = f2fma(v[4], v[4], qa);
                qa = f2fma(v[5], v[5], qa);
                qa = f2fma(v[6], v[6], qa);
                ull qb = f2mul(v[7], v[7]);
                qb = f2fma(v[8], v[8], qb);
                qb = f2fma(v[9], v[9], qb);
                qb = f2fma(v[10], v[10], qb);
                qb = f2fma(v[11], v[11], qb);
                ull qab = f2add(qa, qb);

                h[0] = suw; g[0] = qab;
                #pragma unroll
                for (int m = 0; m < 3; ++m) {
                    ull vn = v[12 + m];
                    ull vo = v[1 + m];
                    suw = f2add(suw, vn);
                    suw = f2fma(vo, NEG1, suw);
                    qab = f2fma(vn, vn, qab);
                    ull von = f2mul(vo, NEG1);
                    qab = f2fma(vo, von, qab);
                    h[m + 1] = suw; g[m + 1] = qab;
                }
            }

            // vertical add (registers)
            #pragma unroll
            for (int c = 0; c < 4; ++c) {
                vUW[c] = f2add(vUW[c], h[c]);
                vAB[c] = f2add(vAB[c], g[c]);
            }

            // ring write: split-half within each 512-ull quantity row
            ull* rw = ring + (size_t)wslot * (2 * IMG_W);
            *(ulonglong2*)(rw + tid * 2)               = make_ulonglong2(h[0], h[1]);
            *(ulonglong2*)(rw + 256 + tid * 2)         = make_ulonglong2(h[2], h[3]);
            *(ulonglong2*)(rw + IMG_W + tid * 2)       = make_ulonglong2(g[0], g[1]);
            *(ulonglong2*)(rw + IMG_W + 256 + tid * 2) = make_ulonglong2(g[2], g[3]);

            // subtract row r-11
            if (r >= 11) {
                int ss = wslot + 1; if (ss == SLOTS) ss = 0;
                const ull* rs = ring + (size_t)ss * (2 * IMG_W);
                ulonglong2 a0 = *(const ulonglong2*)(rs + tid * 2);
                ulonglong2 a1 = *(const ulonglong2*)(rs + 256 + tid * 2);
                ulonglong2 b0 = *(const ulonglong2*)(rs + IMG_W + tid * 2);
                ulonglong2 b1 = *(const ulonglong2*)(rs + IMG_W + 256 + tid * 2);
                vUW[0] = f2fma(a0.x, NEG1, vUW[0]);
                vUW[1] = f2fma(a0.y, NEG1, vUW[1]);
                vUW[2] = f2fma(a1.x, NEG1, vUW[2]);
                vUW[3] = f2fma(a1.y, NEG1, vUW[3]);
                vAB[0] = f2fma(b0.x, NEG1, vAB[0]);
                vAB[1] = f2fma(b0.y, NEG1, vAB[1]);
                vAB[2] = f2fma(b1.x, NEG1, vAB[2]);
                vAB[3] = f2fma(b1.y, NEG1, vAB[3]);
            }

            // epilogue for output row r-10
            if (r >= 10) {
                #pragma unroll
                for (int c = 0; c < 4; ++c) {
                    float A, B;
                    ull sq = f2mul(vUW[c], vUW[c]);
                    float U2, W2;
                    f2up(sq, U2, W2);
                    f2up(vAB[c], A, B);
                    float d  = U2 - W2;
                    float s2 = U2 + W2;
                    float e  = A - B;
                    float f  = A + B;
                    float num1 = fmaf(d, hn2, c1);
                    float num2 = fmaf(d, nhn2, fmaf(e, hn1, c2));
                    float den1 = fmaf(s2, hn2, c1);
                    float sig  = fmaf(s2, nhn2, f * hn1);
                    sig = fmaxf(sig, 0.f);
                    float den = fmaf(den1, sig + c2, 1e-6f);
                    float ssim = __fdividef(num1 * num2, den);
                    acc += fmaxf(fmaf(ssim, -0.5f, 0.5f), 0.f);
                }
            }

            wslot++; if (wslot == SLOTS) wslot = 0;
        }
    }

    // block reduction (reuse smem as float scratch)
    __syncthreads();
    float* red = (float*)smem_u;
    red[tid] = acc;
    __syncthreads();
    #pragma unroll
    for (int s = 64; s > 0; s >>= 1) {
        if (tid < s) red[tid] += red[tid + s];
        __syncthreads();
    }

    if (tid == 0) {
        g_part[bid] = (double)red[0];
        __threadfence();
        unsigned int t = atomicAdd(&g_ticket, 1u);
        s_last = (t == NBLOCKS - 1) ? 1 : 0;
    }
    __syncthreads();

    if (s_last) {
        __threadfence();
        double a = 0.0;
        for (int i = tid; i < NBLOCKS; i += TPB) a += g_part[i];
        double* dred = (double*)smem_u;
        dred[tid] = a;
        __syncthreads();
        #pragma unroll
        for (int s = 64; s > 0; s >>= 1) {
            if (tid < s) dred[tid] += dred[tid + s];
            __syncthreads();
        }
        if (tid == 0) {
            out[0] = (float)(dred[0] / 25165824.0);   // 96*512*512
            g_ticket = 0;                              // reset for next replay
        }
    }
}

extern "C" void kernel_launch(void* const* d_in, const int* in_sizes, int n_in,
                              void* d_out, int out_size) {
    (void)in_sizes; (void)n_in; (void)out_size;
    const float* pred   = (const float*)d_in[0];
    const float* target = (const float*)d_in[1];
    float* out = (float*)d_out;

    range_part<<<NPLANE * 4, 256>>>(pred, target);

    cudaFuncSetAttribute(ssim_kernel, cudaFuncAttributeMaxDynamicSharedMemorySize, SMEM_BYTES);
    ssim_kernel<<<NBLOCKS, TPB, SMEM_BYTES>>>(pred, target, out);
}

// round 5
// speedup vs baseline: 1.9777x; 1.0842x over previous
#include <cuda_runtime.h>

#define NPLANE 96
#define IMG_H 512
#define IMG_W 512
#define PLANE (IMG_H * IMG_W)
#define NSTRIP 6
#define NBLOCKS (NPLANE * NSTRIP)   // 576
#define TPB 128
#define RSLOTS 11
// smem (in ull units):
//   ring:   RSLOTS x [2][256]  (raw {u,w} per col, split-half, thread-private)
//   colsum: UW_E[264] UW_O[264] AB_E[264] AB_O[264]  (132 ulonglong2 each, halo 2)
#define RING_ULL (RSLOTS * 512)
#define CS_ULL   (4 * 264)
#define SMEM_ULL (RING_ULL + CS_ULL)
#define SMEM_BYTES (SMEM_ULL * 8)   // 53504

typedef unsigned long long ull;

__device__ float        g_pmax[NPLANE * 4];
__device__ float        g_pmin[NPLANE * 4];
__device__ double       g_part[NBLOCKS];
__device__ unsigned int g_ticket = 0;

// ---------------- f32x2 packed helpers ----------------
__device__ __forceinline__ ull f2add(ull a, ull b) {
    ull d; asm("add.rn.f32x2 %0,%1,%2;" : "=l"(d) : "l"(a), "l"(b)); return d;
}
__device__ __forceinline__ ull f2mul(ull a, ull b) {
    ull d; asm("mul.rn.f32x2 %0,%1,%2;" : "=l"(d) : "l"(a), "l"(b)); return d;
}
__device__ __forceinline__ ull f2fma(ull a, ull b, ull c) {
    ull d; asm("fma.rn.f32x2 %0,%1,%2,%3;" : "=l"(d) : "l"(a), "l"(b), "l"(c)); return d;
}
__device__ __forceinline__ ull f2pk(float x, float y) {
    ull d; asm("mov.b64 %0,{%1,%2};" : "=l"(d) : "f"(x), "f"(y)); return d;
}
__device__ __forceinline__ void f2up(ull s, float& x, float& y) {
    asm("mov.b64 {%0,%1},%2;" : "=f"(x), "=f"(y) : "l"(s));
}

// ---------------------------------------------------------------------------
// Kernel 1: per-quarter-plane min/max partials (384 blocks)
// ---------------------------------------------------------------------------
__global__ void __launch_bounds__(256) range_part(const float* __restrict__ pred,
                                                  const float* __restrict__ target) {
    __shared__ float sx[256];
    __shared__ float sn[256];
    const int plane = blockIdx.x >> 2;
    const int quad  = blockIdx.x & 3;
    const float4* __restrict__ P = (const float4*)(pred   + (size_t)plane * PLANE) + (size_t)quad * 16384;
    const float4* __restrict__ T = (const float4*)(target + (size_t)plane * PLANE) + (size_t)quad * 16384;
    float mx = -1e30f, mn = 1e30f;
    #pragma unroll 4
    for (int i = threadIdx.x; i < 16384; i += 256) {
        float4 a = __ldg(P + i);
        float4 b = __ldg(T + i);
        float lmx = fmaxf(fmaxf(fmaxf(a.x, b.x), fmaxf(a.y, b.y)),
                          fmaxf(fmaxf(a.z, b.z), fmaxf(a.w, b.w)));
        float lmn = fminf(fminf(fminf(a.x, b.x), fminf(a.y, b.y)),
                          fminf(fminf(a.z, b.z), fminf(a.w, b.w)));
        mx = fmaxf(mx, lmx);
        mn = fminf(mn, lmn);
    }
    sx[threadIdx.x] = mx;
    sn[threadIdx.x] = mn;
    __syncthreads();
    for (int s = 128; s > 0; s >>= 1) {
        if (threadIdx.x < s) {
            sx[threadIdx.x] = fmaxf(sx[threadIdx.x], sx[threadIdx.x + s]);
            sn[threadIdx.x] = fminf(sn[threadIdx.x], sn[threadIdx.x + s]);
        }
        __syncthreads();
    }
    if (threadIdx.x == 0) {
        g_pmax[blockIdx.x] = sx[0];
        g_pmin[blockIdx.x] = sn[0];
    }
}

// horizontal 11-window sliding sums (packed) from split-half E/O arrays
__device__ __forceinline__ void hwindow(const ull* __restrict__ Eb,
                                        const ull* __restrict__ Ob,
                                        int tid, ull NEG1, ull S[4]) {
    ull v[16];
    {
        ulonglong2 q;
        q = *(const ulonglong2*)(Ob + tid * 2);       v[0]  = q.x; v[1]  = q.y;
        q = *(const ulonglong2*)(Eb + (tid + 1) * 2); v[2]  = q.x; v[3]  = q.y;
        q = *(const ulonglong2*)(Ob + (tid + 1) * 2); v[4]  = q.x; v[5]  = q.y;
        q = *(const ulonglong2*)(Eb + (tid + 2) * 2); v[6]  = q.x; v[7]  = q.y;
        q = *(const ulonglong2*)(Ob + (tid + 2) * 2); v[8]  = q.x; v[9]  = q.y;
        q = *(const ulonglong2*)(Eb + (tid + 3) * 2); v[10] = q.x; v[11] = q.y;
        q = *(const ulonglong2*)(Ob + (tid + 3) * 2); v[12] = q.x; v[13] = q.y;
        q = *(const ulonglong2*)(Eb + (tid + 4) * 2); v[14] = q.x; v[15] = q.y;
    }
    ull s01 = f2add(v[1], v[2]);
    ull s23 = f2add(v[3], v[4]);
    ull s45 = f2add(v[5], v[6]);
    ull s67 = f2add(v[7], v[8]);
    ull s89 = f2add(v[9], v[10]);
    ull sA  = f2add(s01, s23);
    ull sB  = f2add(s45, s67);
    ull sC  = f2add(s89, v[11]);
    ull s   = f2add(f2add(sA, sB), sC);
    S[0] = s;
    #pragma unroll
    for (int m = 0; m < 3; ++m) {
        s = f2add(s, v[12 + m]);
        s = f2fma(v[1 + m], NEG1, s);
        S[m + 1] = s;
    }
}

// ---------------------------------------------------------------------------
// Kernel 2: vertical-first fused box SSIM
//   vertical running sums in registers, thread-private 11-slot raw ring,
//   per-row column-sum publish + horizontal sliding window + epilogue.
//   53.5 KB smem -> 4 blocks/SM (16 warps).
// ---------------------------------------------------------------------------
__global__ void __launch_bounds__(TPB, 4) ssim_kernel(const float* __restrict__ pred,
                                                      const float* __restrict__ target,
                                                      float* __restrict__ out) {
    extern __shared__ ull smem_u[];
    ull* ring = smem_u;                 // [RSLOTS][2][256]
    ull* UW_E = smem_u + RING_ULL;      // 264 ull (132 ulonglong2)
    ull* UW_O = UW_E + 264;
    ull* AB_E = UW_O + 264;
    ull* AB_O = AB_E + 264;
    __shared__ int s_last;

    const int bid   = blockIdx.x;
    const int plane = bid / NSTRIP;
    const int strip = bid - plane * NSTRIP;
    const int y0    = strip * 86;
    const int R     = (strip == 5) ? 82 : 86;
    const int KMAX  = R + 10;

    const float* __restrict__ P = pred   + (size_t)plane * PLANE;
    const float* __restrict__ T = target + (size_t)plane * PLANE;

    // per-plane constants from range partials
    const int pb = plane * 4;
    float mx = fmaxf(fmaxf(g_pmax[pb], g_pmax[pb + 1]), fmaxf(g_pmax[pb + 2], g_pmax[pb + 3]));
    float mn = fminf(fminf(g_pmin[pb], g_pmin[pb + 1]), fminf(g_pmin[pb + 2], g_pmin[pb + 3]));
    float dr = fmaxf(mx - mn, 1e-6f);
    const float c1 = (0.01f * dr) * (0.01f * dr);
    const float c2 = (0.03f * dr) * (0.03f * dr);

    const int tid = threadIdx.x;
    const int x0  = tid * 4;

    // zero colsum buffers (halo entries must stay zero)
    for (int z = tid; z < CS_ULL; z += TPB) UW_E[z] = 0ull;

    // prefetch first input row (iy = y0 - 5)
    float4 pp, tt;
    {
        int iy = y0 - 5;
        if (iy >= 0) {
            pp = __ldg((const float4*)(P + (size_t)iy * IMG_W + x0));
            tt = __ldg((const float4*)(T + (size_t)iy * IMG_W + x0));
        } else {
            pp = make_float4(0.f, 0.f, 0.f, 0.f);
            tt = make_float4(0.f, 0.f, 0.f, 0.f);
        }
    }

    const ull NEG1 = f2pk(-1.f, -1.f);
    ull cUW[4] = {0ull, 0ull, 0ull, 0ull};
    ull cAB[4] = {0ull, 0ull, 0ull, 0ull};
    float acc = 0.f;

    const float hn1  = 0.5f / 121.0f;
    const float hn2  = 0.5f / (121.0f * 121.0f);
    const float nhn2 = -hn2;

    int slot = 0;  // k % RSLOTS

    for (int k = 0; k < KMAX; ++k) {
        // pack current row {u,w} per column
        ull n0 = f2pk(pp.x + tt.x, pp.x - tt.x);
        ull n1 = f2pk(pp.y + tt.y, pp.y - tt.y);
        ull n2 = f2pk(pp.z + tt.z, pp.z - tt.z);
        ull n3 = f2pk(pp.w + tt.w, pp.w - tt.w);

        // prefetch next input row
        {
            int iy = y0 - 4 + k;
            if (k + 1 < KMAX && iy >= 0 && iy < IMG_H) {
                pp = __ldg((const float4*)(P + (size_t)iy * IMG_W + x0));
                tt = __ldg((const float4*)(T + (size_t)iy * IMG_W + x0));
            } else {
                pp = make_float4(0.f, 0.f, 0.f, 0.f);
                tt = make_float4(0.f, 0.f, 0.f, 0.f);
            }
        }

        // vertical update (thread-private ring: read old, then overwrite)
        ull* rs = ring + (size_t)slot * 512;
        if (k >= 11) {
            ulonglong2 o0 = *(const ulonglong2*)(rs + 2 * tid);
            ulonglong2 o1 = *(const ulonglong2*)(rs + 256 + 2 * tid);
            cUW[0] = f2fma(o0.x, NEG1, cUW[0]);
            cUW[1] = f2fma(o0.y, NEG1, cUW[1]);
            cUW[2] = f2fma(o1.x, NEG1, cUW[2]);
            cUW[3] = f2fma(o1.y, NEG1, cUW[3]);
            ull m0 = f2mul(o0.x, NEG1);
            ull m1 = f2mul(o0.y, NEG1);
            ull m2 = f2mul(o1.x, NEG1);
            ull m3 = f2mul(o1.y, NEG1);
            cAB[0] = f2fma(o0.x, m0, cAB[0]);
            cAB[1] = f2fma(o0.y, m1, cAB[1]);
            cAB[2] = f2fma(o1.x, m2, cAB[2]);
            cAB[3] = f2fma(o1.y, m3, cAB[3]);
        }
        *(ulonglong2*)(rs + 2 * tid)       = make_ulonglong2(n0, n1);
        *(ulonglong2*)(rs + 256 + 2 * tid) = make_ulonglong2(n2, n3);
        cUW[0] = f2add(cUW[0], n0);
        cUW[1] = f2add(cUW[1], n1);
        cUW[2] = f2add(cUW[2], n2);
        cUW[3] = f2add(cUW[3], n3);
        cAB[0] = f2fma(n0, n0, cAB[0]);
        cAB[1] = f2fma(n1, n1, cAB[1]);
        cAB[2] = f2fma(n2, n2, cAB[2]);
        cAB[3] = f2fma(n3, n3, cAB[3]);

        // publish column sums (single buffer: sync before overwrite, sync after)
        __syncthreads();
        *(ulonglong2*)(UW_E + 2 * (tid + 2)) = make_ulonglong2(cUW[0], cUW[1]);
        *(ulonglong2*)(UW_O + 2 * (tid + 2)) = make_ulonglong2(cUW[2], cUW[3]);
        *(ulonglong2*)(AB_E + 2 * (tid + 2)) = make_ulonglong2(cAB[0], cAB[1]);
        *(ulonglong2*)(AB_O + 2 * (tid + 2)) = make_ulonglong2(cAB[2], cAB[3]);
        __syncthreads();

        // horizontal window + epilogue for output row y = y0 + k - 10
        if (k >= 10) {
            ull SUW[4], SAB[4];
            hwindow(UW_E, UW_O, tid, NEG1, SUW);
            hwindow(AB_E, AB_O, tid, NEG1, SAB);
            #pragma unroll
            for (int c = 0; c < 4; ++c) {
                float A, B;
                ull sq = f2mul(SUW[c], SUW[c]);
                float U2, W2;
                f2up(sq, U2, W2);
                f2up(SAB[c], A, B);
                float d  = U2 - W2;
                float s2 = U2 + W2;
                float e  = A - B;
                float f  = A + B;
                float num1 = fmaf(d, hn2, c1);
                float num2 = fmaf(d, nhn2, fmaf(e, hn1, c2));
                float den1 = fmaf(s2, hn2, c1);
                float sig  = fmaf(s2, nhn2, f * hn1);
                sig = fmaxf(sig, 0.f);
                float den = fmaf(den1, sig + c2, 1e-6f);
                float ssim = __fdividef(num1 * num2, den);
                acc += fmaxf(fmaf(ssim, -0.5f, 0.5f), 0.f);
            }
        }

        slot++; if (slot == RSLOTS) slot = 0;
    }

    // block reduction (reuse smem as float scratch)
    __syncthreads();
    float* red = (float*)smem_u;
    red[tid] = acc;
    __syncthreads();
    #pragma unroll
    for (int s = 64; s > 0; s >>= 1) {
        if (tid < s) red[tid] += red[tid + s];
        __syncthreads();
    }

    if (tid == 0) {
        g_part[bid] = (double)red[0];
        __threadfence();
        unsigned int t = atomicAdd(&g_ticket, 1u);
        s_last = (t == NBLOCKS - 1) ? 1 : 0;
    }
    __syncthreads();

    if (s_last) {
        __threadfence();
        double a = 0.0;
        for (int i = tid; i < NBLOCKS; i += TPB) a += g_part[i];
        double* dred = (double*)smem_u;
        dred[tid] = a;
        __syncthreads();
        #pragma unroll
        for (int s = 64; s > 0; s >>= 1) {
            if (tid < s) dred[tid] += dred[tid + s];
            __syncthreads();
        }
        if (tid == 0) {
            out[0] = (float)(dred[0] / 25165824.0);   // 96*512*512
            g_ticket = 0;                              // reset for next replay
        }
    }
}

extern "C" void kernel_launch(void* const* d_in, const int* in_sizes, int n_in,
                              void* d_out, int out_size) {
    (void)in_sizes; (void)n_in; (void)out_size;
    const float* pred   = (const float*)d_in[0];
    const float* target = (const float*)d_in[1];
    float* out = (float*)d_out;

    range_part<<<NPLANE * 4, 256>>>(pred, target);

    cudaFuncSetAttribute(ssim_kernel, cudaFuncAttributeMaxDynamicSharedMemorySize, SMEM_BYTES);
    ssim_kernel<<<NBLOCKS, TPB, SMEM_BYTES>>>(pred, target, out);
}